// round 12
// baseline (speedup 1.0000x reference)
#include <cuda_runtime.h>
#include <cuda_fp16.h>
#include <cstdint>
#include <math.h>

#define N_ROWS 16384
#define C_ROWS 10000
#define D_DIM  256
#define EPS    1e-6f

#define BM 128
#define BN 128
#define BK 64                 // K elements per chunk (128B rows)
#define KCHUNKS 4             // K=256 / 64
#define TILES_PER_CTA 8
#define NQ (TILES_PER_CTA * KCHUNKS)   // 32 chunk steps per CTA
#define BSTAGES 3
#define A_BYTES 65536         // 128 rows x 256 fp16, as 4 chunks of 16KB
#define B_STAGE_BYTES 16384
#define SMEM_TOTAL (A_BYTES + BSTAGES * B_STAGE_BYTES)   // 112 KB
#define NTHREADS 128          // 4 warps, each 64x64

// ---------------- device scratch (allocation-free rule) ----------------
__device__ __half g_Xs[(size_t)N_ROWS * D_DIM];   // normalized x, fp16
__device__ __half g_Ps[(size_t)C_ROWS * D_DIM];   // normalized p, fp16

// ---------------- helpers ----------------
__device__ __forceinline__ uint32_t smem_u32(const void* p) {
    uint32_t a;
    asm("{ .reg .u64 t; cvta.to.shared.u64 t, %1; cvt.u32.u64 %0, t; }" : "=r"(a) : "l"(p));
    return a;
}
__device__ __forceinline__ void cp_async16(uint32_t dst, const void* src, uint32_t src_bytes) {
    asm volatile("cp.async.cg.shared.global [%0], [%1], 16, %2;"
                 :: "r"(dst), "l"(src), "r"(src_bytes) : "memory");
}
#define CP_COMMIT() asm volatile("cp.async.commit_group;" ::: "memory")
template <int N>
__device__ __forceinline__ void cp_wait() {
    asm volatile("cp.async.wait_group %0;" :: "n"(N) : "memory");
}
__device__ __forceinline__ uint32_t sw128(uint32_t off) { return off ^ ((off >> 3) & 0x70); }

__device__ __forceinline__ void ldsm_x4(uint32_t* r, uint32_t addr) {
    asm volatile("ldmatrix.sync.aligned.m8n8.x4.shared.b16 {%0,%1,%2,%3}, [%4];"
                 : "=r"(r[0]), "=r"(r[1]), "=r"(r[2]), "=r"(r[3]) : "r"(addr));
}
__device__ __forceinline__ void mma_fp16(float* d, const uint32_t* a, const uint32_t* b) {
    asm volatile("mma.sync.aligned.m16n8k16.row.col.f32.f16.f16.f32 "
                 "{%0,%1,%2,%3}, {%4,%5,%6,%7}, {%8,%9}, {%0,%1,%2,%3};"
                 : "+f"(d[0]), "+f"(d[1]), "+f"(d[2]), "+f"(d[3])
                 : "r"(a[0]), "r"(a[1]), "r"(a[2]), "r"(a[3]), "r"(b[0]), "r"(b[1]));
}
__device__ __forceinline__ void stg_cs_v2(float* p, float x, float y) {
    asm volatile("st.global.cs.v2.f32 [%0], {%1, %2};" :: "l"(p), "f"(x), "f"(y) : "memory");
}

// ---------------- fused normalize + fp16 convert for BOTH arrays ----------------
__global__ void normalize_fp16_both(const float* __restrict__ x,
                                    const float* __restrict__ protos,
                                    __half* __restrict__ Xs,
                                    __half* __restrict__ Ps) {
    int warp = (blockIdx.x * blockDim.x + threadIdx.x) >> 5;
    int lane = threadIdx.x & 31;
    const float* src;
    __half* dst;
    if (warp < N_ROWS) {
        src = x + (size_t)warp * D_DIM;
        dst = Xs + (size_t)warp * D_DIM;
    } else {
        int r = warp - N_ROWS;
        if (r >= C_ROWS) return;
        src = protos + (size_t)r * D_DIM;
        dst = Ps + (size_t)r * D_DIM;
    }
    const float4* p = reinterpret_cast<const float4*>(src);
    float4 v0 = p[lane];
    float4 v1 = p[lane + 32];
    float sum = v0.x * v0.x + v0.y * v0.y + v0.z * v0.z + v0.w * v0.w
              + v1.x * v1.x + v1.y * v1.y + v1.z * v1.z + v1.w * v1.w;
#pragma unroll
    for (int o = 16; o > 0; o >>= 1) sum += __shfl_xor_sync(0xffffffffu, sum, o);
    const float inv = 1.0f / fmaxf(sqrtf(sum), EPS);

    __half2 a, b;
    a.x = __float2half_rn(v0.x * inv); a.y = __float2half_rn(v0.y * inv);
    b.x = __float2half_rn(v0.z * inv); b.y = __float2half_rn(v0.w * inv);
    *reinterpret_cast<__half2*>(dst + lane * 4) = a;
    *reinterpret_cast<__half2*>(dst + lane * 4 + 2) = b;
    a.x = __float2half_rn(v1.x * inv); a.y = __float2half_rn(v1.y * inv);
    b.x = __float2half_rn(v1.z * inv); b.y = __float2half_rn(v1.w * inv);
    *reinterpret_cast<__half2*>(dst + (lane + 32) * 4) = a;
    *reinterpret_cast<__half2*>(dst + (lane + 32) * 4 + 2) = b;
}

// ---------------- HMMA fp16 GEMM, A-resident multi-tile CTAs ----------------
// Each CTA: one 128-row M-tile, walks 8 consecutive 128-col N-tiles.
// A (128x256 fp16) resident in smem; B streamed through a 3-stage 16KB ring.
__global__ __launch_bounds__(NTHREADS, 2)
void cosine_hmma_kernel(const __half* __restrict__ Xs,
                        const __half* __restrict__ Ps,
                        float* __restrict__ out) {
    extern __shared__ __align__(1024) char smem[];
    const uint32_t sb = smem_u32(smem);
    const int tid = threadIdx.x;
    const int wid = tid >> 5;
    const int lane = tid & 31;
    const int m0 = blockIdx.y * BM;
    const int ntile0 = blockIdx.x * TILES_PER_CTA;   // first n-tile index

    const int wm = (wid & 1) * 64;     // 0 / 64
    const int wn = (wid >> 1) * 64;    // 0 / 64

    uint32_t aBase[4], aSel[4];
#pragma unroll
    for (int im = 0; im < 4; im++) {
        int rA = wm + im * 16 + (lane & 15);
        aBase[im] = rA * 128;
        aSel[im] = rA & 7;
    }
    uint32_t bBase[4], bSel[4];
#pragma unroll
    for (int in = 0; in < 4; in++) {
        int rB = wn + in * 16 + ((lane >> 4) << 3) + (lane & 7);
        bBase[in] = rB * 128;
        bSel[in] = rB & 7;
    }
    const uint32_t hiA = lane >> 4;
    const uint32_t hiB = (lane >> 3) & 1;

    float acc[4][8][4];
#pragma unroll
    for (int im = 0; im < 4; im++)
#pragma unroll
        for (int j = 0; j < 8; j++)
#pragma unroll
            for (int q = 0; q < 4; q++) acc[im][j][q] = 0.f;

    // ---- prologue: load full A tile (4 chunks of 16KB) as one group ----
    {
#pragma unroll
        for (int i = 0; i < 32; i++) {
            int u = tid + i * NTHREADS;          // 0..4095
            int ka = u >> 10;                     // k-chunk 0..3
            int rem = u & 1023;
            int row = rem >> 3, ch = rem & 7;
            const char* g = (const char*)(Xs + (size_t)(m0 + row) * D_DIM + ka * BK) + ch * 16;
            cp_async16(sb + ka * 16384 + sw128(row * 128 + ch * 16), g, 16);
        }
        CP_COMMIT();
    }

    // B chunk loader: global chunk step q -> tile q>>2, k-chunk q&3, stage q%3
    auto load_b = [&](int q) {
        const int n0 = (ntile0 + (q >> 2)) * BN;
        const int kOff = (q & 3) * BK;
        const uint32_t bA = sb + A_BYTES + (q % BSTAGES) * B_STAGE_BYTES;
#pragma unroll
        for (int i = 0; i < 8; i++) {
            int u = tid + i * NTHREADS;
            int row = u >> 3, ch = u & 7;
            int pr = n0 + row;
            uint32_t ok = (pr < C_ROWS) ? 16u : 0u;
            const char* g = (const char*)(Ps + (size_t)(ok ? pr : 0) * D_DIM + kOff) + ch * 16;
            cp_async16(bA + sw128(row * 128 + ch * 16), g, ok);
        }
        CP_COMMIT();
    };

    load_b(0);
    load_b(1);

    // One kk step: B frags, then A frags interleaved with MMA blocks.
    auto do_kk = [&](uint32_t aChunk, uint32_t bStage, int kk) {
        uint32_t aF[2][4], bF[4][4];
#pragma unroll
        for (int in = 0; in < 4; in++)
            ldsm_x4(bF[in], bStage + bBase[in] + ((((kk * 2 + hiB) ^ bSel[in])) << 4));
        ldsm_x4(aF[0], aChunk + aBase[0] + ((((kk * 2 + hiA) ^ aSel[0])) << 4));
#pragma unroll
        for (int im = 0; im < 4; im++) {
            if (im < 3)
                ldsm_x4(aF[(im + 1) & 1],
                        aChunk + aBase[im + 1] + ((((kk * 2 + hiA) ^ aSel[im + 1])) << 4));
#pragma unroll
            for (int j = 0; j < 8; j++)
                mma_fp16(acc[im][j], aF[im & 1], &bF[j >> 1][(j & 1) * 2]);
        }
    };

    const int mrow0 = m0 + wm + (lane >> 2);
    const int ncolw = wn + (lane & 3) * 2;

    for (int q = 0; q < NQ; q++) {
        const int c = q & 3;
        if (q == NQ - 1) cp_wait<0>(); else cp_wait<1>();
        __syncthreads();   // chunk q resident; all warps done with stage being reused

        const uint32_t aChunk = sb + c * 16384;
        const uint32_t bStage = sb + A_BYTES + (q % BSTAGES) * B_STAGE_BYTES;

        do_kk(aChunk, bStage, 0);
        if (q + 2 < NQ) load_b(q + 2);   // cp.asyncs drain under kk MMAs
#pragma unroll
        for (int kk = 1; kk < 4; kk++) do_kk(aChunk, bStage, kk);

        if (c == 3) {
            // ---- epilogue for this n-tile: streaming stores, then reset acc ----
            const int n0 = (ntile0 + (q >> 2)) * BN;
#pragma unroll
            for (int im = 0; im < 4; im++) {
                const int mA = mrow0 + im * 16;
                float* orow0 = out + (size_t)mA * C_ROWS;
                float* orow1 = out + (size_t)(mA + 8) * C_ROWS;
#pragma unroll
                for (int j = 0; j < 8; j++) {
                    const int n = n0 + ncolw + j * 8;
                    if (n < C_ROWS) {
                        stg_cs_v2(orow0 + n, acc[im][j][0], acc[im][j][1]);
                        stg_cs_v2(orow1 + n, acc[im][j][2], acc[im][j][3]);
                    }
                }
            }
#pragma unroll
            for (int im = 0; im < 4; im++)
#pragma unroll
                for (int j = 0; j < 8; j++)
#pragma unroll
                    for (int qq = 0; qq < 4; qq++) acc[im][j][qq] = 0.f;
        }
    }
}

// ---------------- launch ----------------
extern "C" void kernel_launch(void* const* d_in, const int* in_sizes, int n_in,
                              void* d_out, int out_size) {
    const float* x = (const float*)d_in[0];         // [16384, 256]
    const float* protos = (const float*)d_in[1];    // [10000, 256]
    float* out = (float*)d_out;                     // [16384, 10000]

    __half *Xs, *Ps;
    cudaGetSymbolAddress((void**)&Xs, g_Xs);
    cudaGetSymbolAddress((void**)&Ps, g_Ps);

    int total_warps = N_ROWS + C_ROWS;
    normalize_fp16_both<<<(total_warps * 32 + 255) / 256, 256>>>(x, protos, Xs, Ps);

    cudaFuncSetAttribute(cosine_hmma_kernel,
                         cudaFuncAttributeMaxDynamicSharedMemorySize, SMEM_TOTAL);
    // 10 n-groups x 8 tiles = 80 tiles >= ceil(10000/128)=79; last tile is OOB-guarded.
    dim3 grid(10, N_ROWS / BM);   // (10, 128) = 1280 CTAs
    cosine_hmma_kernel<<<grid, NTHREADS, SMEM_TOTAL>>>(Xs, Ps, out);
}